// round 1
// baseline (speedup 1.0000x reference)
#include <cuda_runtime.h>
#include <math.h>

// Problem constants
#define BB 8
#define NN 4096
#define IND 512
#define DD 512
#define TD 256
#define TOK (BB*NN)          // 32768
#define SCALE_F 0.0625f      // 256^-0.5

// ---------------- scratch (static __device__, no allocation) ----------------
__device__ float g_qI[(size_t)TOK*DD];   // 64MB each
__device__ float g_qM[(size_t)TOK*DD];
__device__ float g_kI[(size_t)TOK*DD];
__device__ float g_kM[(size_t)TOK*DD];
__device__ float g_acc[BB*2*513];        // [b][im][0..511]=Gu, [512]=sum s^2
__device__ float g_PF[4*DD*TD];          // p_i @ f_w   (4 x 512x256)
__device__ float g_cvec[TD];             // (sum biases) @ f_w + f_b
__device__ float g_Wc[(size_t)BB*1536*TD]; // per-batch combined weights [1536x256]

// ---------------- zero accumulators ----------------
__global__ void zero_acc_kernel() {
    int i = blockIdx.x * blockDim.x + threadIdx.x;
    if (i < BB*2*513) g_acc[i] = 0.0f;
}

// ---------------- projection: q/k = l2norm(x@W + b); q also feeds Gu/s2 -----
// grid: (TOK/32, 4)  y: 0=qI 1=qM 2=kI 3=kM ; 256 threads
__global__ void __launch_bounds__(256) proj_kernel(
    const float* __restrict__ xI, const float* __restrict__ xM,
    const float* __restrict__ wqI, const float* __restrict__ bqI,
    const float* __restrict__ wkI, const float* __restrict__ bkI,
    const float* __restrict__ wqM, const float* __restrict__ bqM,
    const float* __restrict__ wkM, const float* __restrict__ bkM,
    const float* __restrict__ wgI, const float* __restrict__ wgM)
{
    const int which = blockIdx.y;
    const float* x;  const float* W;  const float* bias;
    const float* wg = nullptr; float* out;
    switch (which) {
        case 0: x = xI; W = wqI; bias = bqI; wg = wgI; out = g_qI; break;
        case 1: x = xM; W = wqM; bias = bqM; wg = wgM; out = g_qM; break;
        case 2: x = xI; W = wkI; bias = bkI;           out = g_kI; break;
        default:x = xM; W = wkM; bias = bkM;           out = g_kM; break;
    }
    const int tok0 = blockIdx.x * 32;
    const int b    = tok0 >> 12;             // /4096
    float* acc = (which < 2) ? (g_acc + ((size_t)b*2 + which)*513) : nullptr;

    __shared__ float sA[32][8];
    __shared__ float sW[8][512];
    __shared__ float sGu[513];

    const int warp = threadIdx.x >> 5;
    const int lane = threadIdx.x & 31;

    float accv[4][16];
    #pragma unroll
    for (int i = 0; i < 4; i++)
        #pragma unroll
        for (int j = 0; j < 16; j++) accv[i][j] = 0.0f;

    for (int k0 = 0; k0 < IND; k0 += 8) {
        { // A tile: 32x8, one element per thread
            int t  = threadIdx.x >> 3;
            int kk = threadIdx.x & 7;
            sA[t][kk] = x[(size_t)(tok0 + t)*IND + k0 + kk];
        }
        #pragma unroll
        for (int i = 0; i < 4; i++) { // W tile: 8x512 = 1024 float4
            int idx = threadIdx.x + 256*i;
            int kk = idx >> 7, dv = idx & 127;
            float4 v = ((const float4*)(W + (size_t)(k0 + kk)*DD))[dv];
            ((float4*)&sW[kk][0])[dv] = v;
        }
        __syncthreads();
        #pragma unroll
        for (int kk = 0; kk < 8; kk++) {
            float a0 = sA[4*warp+0][kk], a1 = sA[4*warp+1][kk];
            float a2 = sA[4*warp+2][kk], a3 = sA[4*warp+3][kk];
            #pragma unroll
            for (int j = 0; j < 16; j++) {
                float w = sW[kk][lane + 32*j];
                accv[0][j] += a0*w; accv[1][j] += a1*w;
                accv[2][j] += a2*w; accv[3][j] += a3*w;
            }
        }
        __syncthreads();
    }

    // bias + per-token L2 normalize (warp covers all 512 cols of its 4 tokens)
    #pragma unroll
    for (int j = 0; j < 16; j++) {
        float bb = bias[lane + 32*j];
        #pragma unroll
        for (int i = 0; i < 4; i++) accv[i][j] += bb;
    }
    #pragma unroll
    for (int i = 0; i < 4; i++) {
        float ss = 0.0f;
        #pragma unroll
        for (int j = 0; j < 16; j++) ss += accv[i][j]*accv[i][j];
        #pragma unroll
        for (int off = 16; off; off >>= 1) ss += __shfl_xor_sync(0xFFFFFFFFu, ss, off);
        float inv = 1.0f / fmaxf(sqrtf(ss), 1e-12f);
        #pragma unroll
        for (int j = 0; j < 16; j++) accv[i][j] *= inv;
    }

    // store normalized projection
    #pragma unroll
    for (int i = 0; i < 4; i++) {
        size_t base = (size_t)(tok0 + 4*warp + i)*DD;
        #pragma unroll
        for (int j = 0; j < 16; j++) out[base + lane + 32*j] = accv[i][j];
    }

    // q path: s = q.wg ; accumulate Gu += s*q and S2 += s^2 (block-local, then global)
    if (acc) {
        for (int c = threadIdx.x; c < 513; c += 256) sGu[c] = 0.0f;
        __syncthreads();
        float s[4];
        #pragma unroll
        for (int i = 0; i < 4; i++) {
            float v = 0.0f;
            #pragma unroll
            for (int j = 0; j < 16; j++) v += accv[i][j] * wg[lane + 32*j];
            #pragma unroll
            for (int off = 16; off; off >>= 1) v += __shfl_xor_sync(0xFFFFFFFFu, v, off);
            s[i] = v;
        }
        #pragma unroll
        for (int j = 0; j < 16; j++) {
            float g = s[0]*accv[0][j] + s[1]*accv[1][j] + s[2]*accv[2][j] + s[3]*accv[3][j];
            atomicAdd(&sGu[lane + 32*j], g);
        }
        if (lane == 0)
            atomicAdd(&sGu[512], s[0]*s[0] + s[1]*s[1] + s[2]*s[2] + s[3]*s[3]);
        __syncthreads();
        for (int c = threadIdx.x; c < 513; c += 256) atomicAdd(&acc[c], sGu[c]);
    }
}

// ---------------- P_iF = p_i @ f_w  (batch-independent) ----------------
// grid (16, 4): x=row tile of 32, y=matrix; 256 threads
__global__ void __launch_bounds__(256) pf_kernel(
    const float* __restrict__ p1, const float* __restrict__ p2,
    const float* __restrict__ p3, const float* __restrict__ p4,
    const float* __restrict__ fw)
{
    const float* P[4] = {p1, p2, p3, p4};
    const float* p = P[blockIdx.y];
    float* out = g_PF + (size_t)blockIdx.y * DD * TD;
    const int r0 = blockIdx.x * 32;

    __shared__ float sA[32][8];
    __shared__ float sF[8][256];

    const int warp = threadIdx.x >> 5;
    const int lane = threadIdx.x & 31;
    float accv[4][8];
    #pragma unroll
    for (int i = 0; i < 4; i++)
        #pragma unroll
        for (int j = 0; j < 8; j++) accv[i][j] = 0.0f;

    for (int k0 = 0; k0 < DD; k0 += 8) {
        {
            int t = threadIdx.x >> 3, kk = threadIdx.x & 7;
            sA[t][kk] = p[(size_t)(r0 + t)*DD + k0 + kk];
        }
        #pragma unroll
        for (int i = 0; i < 2; i++) {
            int idx = threadIdx.x + 256*i;
            int kk = idx >> 6, dv = idx & 63;
            ((float4*)&sF[kk][0])[dv] = ((const float4*)(fw + (size_t)(k0 + kk)*TD))[dv];
        }
        __syncthreads();
        #pragma unroll
        for (int kk = 0; kk < 8; kk++) {
            float a0 = sA[4*warp+0][kk], a1 = sA[4*warp+1][kk];
            float a2 = sA[4*warp+2][kk], a3 = sA[4*warp+3][kk];
            #pragma unroll
            for (int j = 0; j < 8; j++) {
                float w = sF[kk][lane + 32*j];
                accv[0][j] += a0*w; accv[1][j] += a1*w;
                accv[2][j] += a2*w; accv[3][j] += a3*w;
            }
        }
        __syncthreads();
    }
    #pragma unroll
    for (int i = 0; i < 4; i++) {
        size_t base = (size_t)(r0 + 4*warp + i)*TD;
        #pragma unroll
        for (int j = 0; j < 8; j++) out[base + lane + 32*j] = accv[i][j];
    }
}

// ---------------- cvec = (b1+b2+b3+b4)@f_w + f_b ----------------
__global__ void cvec_kernel(
    const float* __restrict__ b1, const float* __restrict__ b2,
    const float* __restrict__ b3, const float* __restrict__ b4,
    const float* __restrict__ fw, const float* __restrict__ fb)
{
    int c = threadIdx.x;
    float s = fb[c];
    for (int e = 0; e < DD; e++)
        s += (b1[e] + b2[e] + b3[e] + b4[e]) * fw[(size_t)e*TD + c];
    g_cvec[c] = s;
}

// ---------------- per-batch combined weights Wc [1536x256] ----------------
// rows 0-511:   G_I*P1F + G_M*P4F   (multiplies k_I)
// rows 512-1023:G_I*P2F + G_M*P3F   (multiplies k_M)
// rows 1024+:   f_w                  (multiplies q_I+q_M)
// grid (1536, 8); 256 threads = one row x one col each
__global__ void combine_kernel(const float* __restrict__ fw) {
    const int b = blockIdx.y;
    const int r = blockIdx.x;
    const int c = threadIdx.x;
    const float* acc = g_acc + (size_t)b*2*513;
    float v;
    if (r < 1024) {
        int rr = r & 511;
        float nI = fmaxf(SCALE_F * sqrtf(acc[512]),       1e-12f);
        float nM = fmaxf(SCALE_F * sqrtf(acc[513 + 512]), 1e-12f);
        float GI = SCALE_F * acc[rr]       / nI;
        float GM = SCALE_F * acc[513 + rr] / nM;
        if (r < 512)
            v = GI * g_PF[0*DD*TD + (size_t)rr*TD + c] + GM * g_PF[3*DD*TD + (size_t)rr*TD + c];
        else
            v = GI * g_PF[1*DD*TD + (size_t)rr*TD + c] + GM * g_PF[2*DD*TD + (size_t)rr*TD + c];
    } else {
        v = fw[(size_t)(r - 1024)*TD + c];
    }
    g_Wc[((size_t)b*1536 + r)*TD + c] = v;
}

// ---------------- final: out = [kI|kM|qI+qM] @ Wc_b + cvec ----------------
// grid TOK/32; 256 threads
__global__ void __launch_bounds__(256) final_kernel(float* __restrict__ outp) {
    const int tok0 = blockIdx.x * 32;
    const int b = tok0 >> 12;
    const float* Wc = g_Wc + (size_t)b*1536*TD;

    __shared__ float sA[32][8];
    __shared__ float sW[8][256];

    const int warp = threadIdx.x >> 5;
    const int lane = threadIdx.x & 31;
    float accv[4][8];
    #pragma unroll
    for (int i = 0; i < 4; i++)
        #pragma unroll
        for (int j = 0; j < 8; j++) accv[i][j] = 0.0f;

    for (int k0 = 0; k0 < 1536; k0 += 8) {
        {
            int t = threadIdx.x >> 3, kk = threadIdx.x & 7;
            int k = k0 + kk;
            size_t tb = (size_t)(tok0 + t)*DD;
            float a;
            if (k < 512)       a = g_kI[tb + k];
            else if (k < 1024) a = g_kM[tb + (k - 512)];
            else               a = g_qI[tb + (k - 1024)] + g_qM[tb + (k - 1024)];
            sA[t][kk] = a;
        }
        #pragma unroll
        for (int i = 0; i < 2; i++) {
            int idx = threadIdx.x + 256*i;
            int kk = idx >> 6, dv = idx & 63;
            ((float4*)&sW[kk][0])[dv] = ((const float4*)(Wc + (size_t)(k0 + kk)*TD))[dv];
        }
        __syncthreads();
        #pragma unroll
        for (int kk = 0; kk < 8; kk++) {
            float a0 = sA[4*warp+0][kk], a1 = sA[4*warp+1][kk];
            float a2 = sA[4*warp+2][kk], a3 = sA[4*warp+3][kk];
            #pragma unroll
            for (int j = 0; j < 8; j++) {
                float w = sW[kk][lane + 32*j];
                accv[0][j] += a0*w; accv[1][j] += a1*w;
                accv[2][j] += a2*w; accv[3][j] += a3*w;
            }
        }
        __syncthreads();
    }
    float cv[8];
    #pragma unroll
    for (int j = 0; j < 8; j++) cv[j] = g_cvec[lane + 32*j];
    #pragma unroll
    for (int i = 0; i < 4; i++) {
        size_t base = (size_t)(tok0 + 4*warp + i)*TD;
        #pragma unroll
        for (int j = 0; j < 8; j++) outp[base + lane + 32*j] = accv[i][j] + cv[j];
    }
}

// ---------------- launch ----------------
extern "C" void kernel_launch(void* const* d_in, const int* in_sizes, int n_in,
                              void* d_out, int out_size)
{
    const float* xI  = (const float*)d_in[0];
    const float* xM  = (const float*)d_in[1];
    const float* wqI = (const float*)d_in[2];
    const float* bqI = (const float*)d_in[3];
    const float* wkI = (const float*)d_in[4];
    const float* bkI = (const float*)d_in[5];
    const float* wqM = (const float*)d_in[6];
    const float* bqM = (const float*)d_in[7];
    const float* wkM = (const float*)d_in[8];
    const float* bkM = (const float*)d_in[9];
    const float* wgI = (const float*)d_in[10];
    const float* wgM = (const float*)d_in[11];
    const float* p1w = (const float*)d_in[12];
    const float* p1b = (const float*)d_in[13];
    const float* p2w = (const float*)d_in[14];
    const float* p2b = (const float*)d_in[15];
    const float* p3w = (const float*)d_in[16];
    const float* p3b = (const float*)d_in[17];
    const float* p4w = (const float*)d_in[18];
    const float* p4b = (const float*)d_in[19];
    const float* fw  = (const float*)d_in[20];
    const float* fb  = (const float*)d_in[21];
    float* out = (float*)d_out;

    zero_acc_kernel<<<33, 256>>>();
    proj_kernel<<<dim3(TOK/32, 4), 256>>>(xI, xM, wqI, bqI, wkI, bkI,
                                          wqM, bqM, wkM, bkM, wgI, wgM);
    pf_kernel<<<dim3(16, 4), 256>>>(p1w, p2w, p3w, p4w, fw);
    cvec_kernel<<<1, 256>>>(p1b, p2b, p3b, p4b, fw, fb);
    combine_kernel<<<dim3(1536, 8), 256>>>(fw);
    final_kernel<<<TOK/32, 256>>>(out);
}

// round 2
// speedup vs baseline: 1.0005x; 1.0005x over previous
#include <cuda_runtime.h>
#include <math.h>

// Problem constants
#define BB 8
#define NN 4096
#define IND 512
#define DD 512
#define TD 256
#define TOK (BB*NN)          // 32768
#define SCALE_F 0.0625f      // 256^-0.5

// ---------------- scratch (static __device__, no allocation) ----------------
__device__ float g_qI[(size_t)TOK*DD];   // 64MB each
__device__ float g_qM[(size_t)TOK*DD];
__device__ float g_kI[(size_t)TOK*DD];
__device__ float g_kM[(size_t)TOK*DD];
__device__ float g_acc[BB*2*513];        // [b][im][0..511]=Gu, [512]=sum s^2
__device__ float g_PF[4*DD*TD];          // p_i @ f_w   (4 x 512x256)
__device__ float g_cvec[TD];             // (sum biases) @ f_w + f_b
__device__ float g_Wc[(size_t)BB*1536*TD]; // per-batch combined weights [1536x256]

// ---------------- zero accumulators ----------------
__global__ void zero_acc_kernel() {
    int i = blockIdx.x * blockDim.x + threadIdx.x;
    if (i < BB*2*513) g_acc[i] = 0.0f;
}

// ---------------- projection: q/k = l2norm(x@W + b); q also feeds Gu/s2 -----
// grid: (TOK/32, 4)  y: 0=qI 1=qM 2=kI 3=kM ; 256 threads
__global__ void __launch_bounds__(256) proj_kernel(
    const float* __restrict__ xI, const float* __restrict__ xM,
    const float* __restrict__ wqI, const float* __restrict__ bqI,
    const float* __restrict__ wkI, const float* __restrict__ bkI,
    const float* __restrict__ wqM, const float* __restrict__ bqM,
    const float* __restrict__ wkM, const float* __restrict__ bkM,
    const float* __restrict__ wgI, const float* __restrict__ wgM)
{
    const int which = blockIdx.y;
    const float* x;  const float* W;  const float* bias;
    const float* wg = nullptr; float* out;
    switch (which) {
        case 0: x = xI; W = wqI; bias = bqI; wg = wgI; out = g_qI; break;
        case 1: x = xM; W = wqM; bias = bqM; wg = wgM; out = g_qM; break;
        case 2: x = xI; W = wkI; bias = bkI;           out = g_kI; break;
        default:x = xM; W = wkM; bias = bkM;           out = g_kM; break;
    }
    const int tok0 = blockIdx.x * 32;
    const int b    = tok0 >> 12;             // /4096
    float* acc = (which < 2) ? (g_acc + ((size_t)b*2 + which)*513) : nullptr;

    __shared__ float sA[32][8];
    __shared__ float sW[8][512];
    __shared__ float sGu[513];

    const int warp = threadIdx.x >> 5;
    const int lane = threadIdx.x & 31;

    float accv[4][16];
    #pragma unroll
    for (int i = 0; i < 4; i++)
        #pragma unroll
        for (int j = 0; j < 16; j++) accv[i][j] = 0.0f;

    for (int k0 = 0; k0 < IND; k0 += 8) {
        { // A tile: 32x8, one element per thread
            int t  = threadIdx.x >> 3;
            int kk = threadIdx.x & 7;
            sA[t][kk] = x[(size_t)(tok0 + t)*IND + k0 + kk];
        }
        #pragma unroll
        for (int i = 0; i < 4; i++) { // W tile: 8x512 = 1024 float4
            int idx = threadIdx.x + 256*i;
            int kk = idx >> 7, dv = idx & 127;
            float4 v = ((const float4*)(W + (size_t)(k0 + kk)*DD))[dv];
            ((float4*)&sW[kk][0])[dv] = v;
        }
        __syncthreads();
        #pragma unroll
        for (int kk = 0; kk < 8; kk++) {
            float a0 = sA[4*warp+0][kk], a1 = sA[4*warp+1][kk];
            float a2 = sA[4*warp+2][kk], a3 = sA[4*warp+3][kk];
            #pragma unroll
            for (int j = 0; j < 16; j++) {
                float w = sW[kk][lane + 32*j];
                accv[0][j] += a0*w; accv[1][j] += a1*w;
                accv[2][j] += a2*w; accv[3][j] += a3*w;
            }
        }
        __syncthreads();
    }

    // bias + per-token L2 normalize (warp covers all 512 cols of its 4 tokens)
    #pragma unroll
    for (int j = 0; j < 16; j++) {
        float bb = bias[lane + 32*j];
        #pragma unroll
        for (int i = 0; i < 4; i++) accv[i][j] += bb;
    }
    #pragma unroll
    for (int i = 0; i < 4; i++) {
        float ss = 0.0f;
        #pragma unroll
        for (int j = 0; j < 16; j++) ss += accv[i][j]*accv[i][j];
        #pragma unroll
        for (int off = 16; off; off >>= 1) ss += __shfl_xor_sync(0xFFFFFFFFu, ss, off);
        float inv = 1.0f / fmaxf(sqrtf(ss), 1e-12f);
        #pragma unroll
        for (int j = 0; j < 16; j++) accv[i][j] *= inv;
    }

    // store normalized projection
    #pragma unroll
    for (int i = 0; i < 4; i++) {
        size_t base = (size_t)(tok0 + 4*warp + i)*DD;
        #pragma unroll
        for (int j = 0; j < 16; j++) out[base + lane + 32*j] = accv[i][j];
    }

    // q path: s = q.wg ; accumulate Gu += s*q and S2 += s^2 (block-local, then global)
    if (acc) {
        for (int c = threadIdx.x; c < 513; c += 256) sGu[c] = 0.0f;
        __syncthreads();
        float s[4];
        #pragma unroll
        for (int i = 0; i < 4; i++) {
            float v = 0.0f;
            #pragma unroll
            for (int j = 0; j < 16; j++) v += accv[i][j] * wg[lane + 32*j];
            #pragma unroll
            for (int off = 16; off; off >>= 1) v += __shfl_xor_sync(0xFFFFFFFFu, v, off);
            s[i] = v;
        }
        #pragma unroll
        for (int j = 0; j < 16; j++) {
            float g = s[0]*accv[0][j] + s[1]*accv[1][j] + s[2]*accv[2][j] + s[3]*accv[3][j];
            atomicAdd(&sGu[lane + 32*j], g);
        }
        if (lane == 0)
            atomicAdd(&sGu[512], s[0]*s[0] + s[1]*s[1] + s[2]*s[2] + s[3]*s[3]);
        __syncthreads();
        for (int c = threadIdx.x; c < 513; c += 256) atomicAdd(&acc[c], sGu[c]);
    }
}

// ---------------- P_iF = p_i @ f_w  (batch-independent) ----------------
// grid (16, 4): x=row tile of 32, y=matrix; 256 threads
__global__ void __launch_bounds__(256) pf_kernel(
    const float* __restrict__ p1, const float* __restrict__ p2,
    const float* __restrict__ p3, const float* __restrict__ p4,
    const float* __restrict__ fw)
{
    const float* P[4] = {p1, p2, p3, p4};
    const float* p = P[blockIdx.y];
    float* out = g_PF + (size_t)blockIdx.y * DD * TD;
    const int r0 = blockIdx.x * 32;

    __shared__ float sA[32][8];
    __shared__ float sF[8][256];

    const int warp = threadIdx.x >> 5;
    const int lane = threadIdx.x & 31;
    float accv[4][8];
    #pragma unroll
    for (int i = 0; i < 4; i++)
        #pragma unroll
        for (int j = 0; j < 8; j++) accv[i][j] = 0.0f;

    for (int k0 = 0; k0 < DD; k0 += 8) {
        {
            int t = threadIdx.x >> 3, kk = threadIdx.x & 7;
            sA[t][kk] = p[(size_t)(r0 + t)*DD + k0 + kk];
        }
        #pragma unroll
        for (int i = 0; i < 2; i++) {
            int idx = threadIdx.x + 256*i;
            int kk = idx >> 6, dv = idx & 63;
            ((float4*)&sF[kk][0])[dv] = ((const float4*)(fw + (size_t)(k0 + kk)*TD))[dv];
        }
        __syncthreads();
        #pragma unroll
        for (int kk = 0; kk < 8; kk++) {
            float a0 = sA[4*warp+0][kk], a1 = sA[4*warp+1][kk];
            float a2 = sA[4*warp+2][kk], a3 = sA[4*warp+3][kk];
            #pragma unroll
            for (int j = 0; j < 8; j++) {
                float w = sF[kk][lane + 32*j];
                accv[0][j] += a0*w; accv[1][j] += a1*w;
                accv[2][j] += a2*w; accv[3][j] += a3*w;
            }
        }
        __syncthreads();
    }
    #pragma unroll
    for (int i = 0; i < 4; i++) {
        size_t base = (size_t)(r0 + 4*warp + i)*TD;
        #pragma unroll
        for (int j = 0; j < 8; j++) out[base + lane + 32*j] = accv[i][j];
    }
}

// ---------------- cvec = (b1+b2+b3+b4)@f_w + f_b ----------------
__global__ void cvec_kernel(
    const float* __restrict__ b1, const float* __restrict__ b2,
    const float* __restrict__ b3, const float* __restrict__ b4,
    const float* __restrict__ fw, const float* __restrict__ fb)
{
    int c = threadIdx.x;
    float s = fb[c];
    for (int e = 0; e < DD; e++)
        s += (b1[e] + b2[e] + b3[e] + b4[e]) * fw[(size_t)e*TD + c];
    g_cvec[c] = s;
}

// ---------------- per-batch combined weights Wc [1536x256] ----------------
// rows 0-511:   G_I*P1F + G_M*P4F   (multiplies k_I)
// rows 512-1023:G_I*P2F + G_M*P3F   (multiplies k_M)
// rows 1024+:   f_w                  (multiplies q_I+q_M)
// grid (1536, 8); 256 threads = one row x one col each
__global__ void combine_kernel(const float* __restrict__ fw) {
    const int b = blockIdx.y;
    const int r = blockIdx.x;
    const int c = threadIdx.x;
    const float* acc = g_acc + (size_t)b*2*513;
    float v;
    if (r < 1024) {
        int rr = r & 511;
        float nI = fmaxf(SCALE_F * sqrtf(acc[512]),       1e-12f);
        float nM = fmaxf(SCALE_F * sqrtf(acc[513 + 512]), 1e-12f);
        float GI = SCALE_F * acc[rr]       / nI;
        float GM = SCALE_F * acc[513 + rr] / nM;
        if (r < 512)
            v = GI * g_PF[0*DD*TD + (size_t)rr*TD + c] + GM * g_PF[3*DD*TD + (size_t)rr*TD + c];
        else
            v = GI * g_PF[1*DD*TD + (size_t)rr*TD + c] + GM * g_PF[2*DD*TD + (size_t)rr*TD + c];
    } else {
        v = fw[(size_t)(r - 1024)*TD + c];
    }
    g_Wc[((size_t)b*1536 + r)*TD + c] = v;
}

// ---------------- final: out = [kI|kM|qI+qM] @ Wc_b + cvec ----------------
// grid TOK/32; 256 threads
__global__ void __launch_bounds__(256) final_kernel(float* __restrict__ outp) {
    const int tok0 = blockIdx.x * 32;
    const int b = tok0 >> 12;
    const float* Wc = g_Wc + (size_t)b*1536*TD;

    __shared__ float sA[32][8];
    __shared__ float sW[8][256];

    const int warp = threadIdx.x >> 5;
    const int lane = threadIdx.x & 31;
    float accv[4][8];
    #pragma unroll
    for (int i = 0; i < 4; i++)
        #pragma unroll
        for (int j = 0; j < 8; j++) accv[i][j] = 0.0f;

    for (int k0 = 0; k0 < 1536; k0 += 8) {
        {
            int t = threadIdx.x >> 3, kk = threadIdx.x & 7;
            int k = k0 + kk;
            size_t tb = (size_t)(tok0 + t)*DD;
            float a;
            if (k < 512)       a = g_kI[tb + k];
            else if (k < 1024) a = g_kM[tb + (k - 512)];
            else               a = g_qI[tb + (k - 1024)] + g_qM[tb + (k - 1024)];
            sA[t][kk] = a;
        }
        #pragma unroll
        for (int i = 0; i < 2; i++) {
            int idx = threadIdx.x + 256*i;
            int kk = idx >> 6, dv = idx & 63;
            ((float4*)&sW[kk][0])[dv] = ((const float4*)(Wc + (size_t)(k0 + kk)*TD))[dv];
        }
        __syncthreads();
        #pragma unroll
        for (int kk = 0; kk < 8; kk++) {
            float a0 = sA[4*warp+0][kk], a1 = sA[4*warp+1][kk];
            float a2 = sA[4*warp+2][kk], a3 = sA[4*warp+3][kk];
            #pragma unroll
            for (int j = 0; j < 8; j++) {
                float w = sW[kk][lane + 32*j];
                accv[0][j] += a0*w; accv[1][j] += a1*w;
                accv[2][j] += a2*w; accv[3][j] += a3*w;
            }
        }
        __syncthreads();
    }
    float cv[8];
    #pragma unroll
    for (int j = 0; j < 8; j++) cv[j] = g_cvec[lane + 32*j];
    #pragma unroll
    for (int i = 0; i < 4; i++) {
        size_t base = (size_t)(tok0 + 4*warp + i)*TD;
        #pragma unroll
        for (int j = 0; j < 8; j++) outp[base + lane + 32*j] = accv[i][j] + cv[j];
    }
}

// ---------------- launch ----------------
extern "C" void kernel_launch(void* const* d_in, const int* in_sizes, int n_in,
                              void* d_out, int out_size)
{
    const float* xI  = (const float*)d_in[0];
    const float* xM  = (const float*)d_in[1];
    const float* wqI = (const float*)d_in[2];
    const float* bqI = (const float*)d_in[3];
    const float* wkI = (const float*)d_in[4];
    const float* bkI = (const float*)d_in[5];
    const float* wqM = (const float*)d_in[6];
    const float* bqM = (const float*)d_in[7];
    const float* wkM = (const float*)d_in[8];
    const float* bkM = (const float*)d_in[9];
    const float* wgI = (const float*)d_in[10];
    const float* wgM = (const float*)d_in[11];
    const float* p1w = (const float*)d_in[12];
    const float* p1b = (const float*)d_in[13];
    const float* p2w = (const float*)d_in[14];
    const float* p2b = (const float*)d_in[15];
    const float* p3w = (const float*)d_in[16];
    const float* p3b = (const float*)d_in[17];
    const float* p4w = (const float*)d_in[18];
    const float* p4b = (const float*)d_in[19];
    const float* fw  = (const float*)d_in[20];
    const float* fb  = (const float*)d_in[21];
    float* out = (float*)d_out;

    zero_acc_kernel<<<33, 256>>>();
    proj_kernel<<<dim3(TOK/32, 4), 256>>>(xI, xM, wqI, bqI, wkI, bkI,
                                          wqM, bqM, wkM, bkM, wgI, wgM);
    pf_kernel<<<dim3(16, 4), 256>>>(p1w, p2w, p3w, p4w, fw);
    cvec_kernel<<<1, 256>>>(p1b, p2b, p3b, p4b, fw, fb);
    combine_kernel<<<dim3(1536, 8), 256>>>(fw);
    final_kernel<<<TOK/32, 256>>>(out);
}

// round 5
// speedup vs baseline: 3.0044x; 3.0030x over previous
#include <cuda_runtime.h>
#include <cuda_bf16.h>
#include <math.h>
#include <stdint.h>

#define BB 8
#define NN 4096
#define DD 512
#define TD 256
#define TOK (BB*NN)
#define SCALE_F 0.0625f

// ---------------- static scratch ----------------
__device__ __nv_bfloat16 g_xhi[2][(size_t)TOK*DD];   // x hi/lo planes (I, M)
__device__ __nv_bfloat16 g_xlo[2][(size_t)TOK*DD];
__device__ float         g_raw[4][(size_t)TOK*DD];   // raw proj output (pre-bias/norm)
__device__ __nv_bfloat16 g_phi[4][(size_t)TOK*DD];   // normalized q/k hi planes [qI,qM,kI,kM]
__device__ __nv_bfloat16 g_plo[4][(size_t)TOK*DD];
__device__ __nv_bfloat16 g_Wthi[4][DD*DD];           // W^T planes [mat][n][k]
__device__ __nv_bfloat16 g_Wtlo[4][DD*DD];
__device__ __nv_bfloat16 g_Wchi[BB][TD*2048];        // combined W^T [b][n][k]
__device__ __nv_bfloat16 g_Wclo[BB][TD*2048];
__device__ float g_fwT[TD*DD];                       // f_w^T [n][e]
__device__ float g_PFt[4][TD*DD];                    // (p_i@f_w)^T [n][k]
__device__ float g_acc[BB*2*513];
__device__ float g_cvec[TD];

// ---------------- helpers ----------------
__device__ __forceinline__ uint32_t smem_u32(const void* p) {
    uint32_t a;
    asm("{ .reg .u64 t; cvta.to.shared.u64 t, %1; cvt.u32.u64 %0, t; }" : "=r"(a) : "l"(p));
    return a;
}
__device__ __forceinline__ void cp16(uint32_t s, const void* g) {
    asm volatile("cp.async.cg.shared.global [%0], [%1], 16;" :: "r"(s), "l"(g));
}
__device__ __forceinline__ void cp_commit() {
    asm volatile("cp.async.commit_group;");
}
__device__ __forceinline__ void cp_wait1() {
    asm volatile("cp.async.wait_group 1;");
}
__device__ __forceinline__ void cp_wait0() {
    asm volatile("cp.async.wait_group 0;");
}
__device__ __forceinline__ void ldsm4(uint32_t* r, uint32_t addr) {
    asm volatile("ldmatrix.sync.aligned.m8n8.x4.shared.b16 {%0,%1,%2,%3}, [%4];"
        : "=r"(r[0]), "=r"(r[1]), "=r"(r[2]), "=r"(r[3]) : "r"(addr));
}
__device__ __forceinline__ void mma_bf16(float* c, const uint32_t* a, uint32_t b0, uint32_t b1) {
    asm volatile("mma.sync.aligned.m16n8k16.row.col.f32.bf16.bf16.f32 "
        "{%0,%1,%2,%3}, {%4,%5,%6,%7}, {%8,%9}, {%0,%1,%2,%3};"
        : "+f"(c[0]), "+f"(c[1]), "+f"(c[2]), "+f"(c[3])
        : "r"(a[0]), "r"(a[1]), "r"(a[2]), "r"(a[3]), "r"(b0), "r"(b1));
}

// SMEM per buffer: A planes 2x16KB, B planes 2x16KB -> 64KB; double buffered 128KB
#define BUFSZ 65536
#define SMEM_TOTAL 131072

// ---------------- MMA GEMM (MODE 0 = proj x@W -> raw fp32; MODE 1 = final -> out) -----
// grid: (TOK/128, ntiles, which)  block 256
template<int MODE>
__global__ void __launch_bounds__(256) mma_gemm(float* __restrict__ outp)
{
    extern __shared__ char smem[];
    const uint32_t sb = smem_u32(smem);
    __shared__ float sbias[128];

    const int tid = threadIdx.x, wid = tid >> 5, lane = tid & 31;
    const int tok0 = blockIdx.x * 128;
    const int n0   = blockIdx.y * 128;
    const int which = (MODE == 0) ? blockIdx.z : 0;
    const int batch = tok0 >> 12;
    const int NC = (MODE == 0) ? 8 : 32;

    if (MODE == 1 && tid < 128) sbias[tid] = g_cvec[n0 + tid];

    const int xsel = which & 1;

    // ---- issue chunk c into buffer (cp.async) ----
    auto issue = [&](int c, int buf) {
        uint32_t abase = sb + buf*BUFSZ;
        uint32_t bbase = abase + 32768;
        // A: 2 planes x 128 rows x 64 bf16 (8 units of 16B per row)
        #pragma unroll
        for (int it = 0; it < 8; it++) {
            int v = it*256 + tid;
            int plane = v >> 10, idx = v & 1023, r = idx >> 3, u = idx & 7;
            const __nv_bfloat16* src;
            if (MODE == 0) {
                src = (plane ? g_xlo[xsel] : g_xhi[xsel])
                    + (size_t)(tok0 + r)*512 + c*64 + u*8;
            } else {
                int mat = (c >> 3) ^ 2;     // segs: kI,kM,qI,qM -> mats 2,3,0,1
                src = (plane ? g_plo[mat] : g_phi[mat])
                    + (size_t)(tok0 + r)*512 + (c & 7)*64 + u*8;
            }
            cp16(abase + plane*16384 + r*128 + ((u ^ (r & 7)) << 4), src);
        }
        // B: 2 planes x 128 n-rows x 64 bf16
        #pragma unroll
        for (int it = 0; it < 8; it++) {
            int v = it*256 + tid;
            int plane = v >> 10, idx = v & 1023, r = idx >> 3, u = idx & 7;
            const __nv_bfloat16* src;
            if (MODE == 0) {
                src = (plane ? g_Wtlo[which] : g_Wthi[which])
                    + (size_t)(n0 + r)*512 + c*64 + u*8;
            } else {
                src = (plane ? g_Wclo[batch] : g_Wchi[batch])
                    + (size_t)(n0 + r)*2048 + c*64 + u*8;
            }
            cp16(bbase + plane*16384 + r*128 + ((u ^ (r & 7)) << 4), src);
        }
        cp_commit();
    };

    float acc[2][8][4];
    #pragma unroll
    for (int mt = 0; mt < 2; mt++)
        #pragma unroll
        for (int nt = 0; nt < 8; nt++)
            #pragma unroll
            for (int e = 0; e < 4; e++) acc[mt][nt][e] = 0.f;

    const int wm = wid >> 1, wn = wid & 1;      // warps 4x2 -> 32m x 64n per warp
    const int mwb = wm * 32, nwb = wn * 64;

    issue(0, 0);
    issue(1, 1);

    for (int c = 0; c < NC; c++) {
        if (c < NC - 1) cp_wait1(); else cp_wait0();
        __syncthreads();
        const int buf = c & 1;
        uint32_t abase = sb + buf*BUFSZ;
        uint32_t bbase = abase + 32768;

        #pragma unroll
        for (int k16 = 0; k16 < 4; k16++) {
            uint32_t ah[2][4], al[2][4], bh[4][4], bl[4][4];
            #pragma unroll
            for (int mt = 0; mt < 2; mt++) {
                int row = mwb + mt*16 + (lane & 15);
                int kb  = k16*2 + (lane >> 4);
                uint32_t off = row*128 + ((kb ^ (row & 7)) << 4);
                ldsm4(ah[mt], abase + off);
                ldsm4(al[mt], abase + 16384 + off);
            }
            #pragma unroll
            for (int bt = 0; bt < 4; bt++) {
                int row = nwb + bt*16 + ((lane >> 4) << 3) + (lane & 7);
                int kb  = k16*2 + ((lane >> 3) & 1);
                uint32_t off = row*128 + ((kb ^ (row & 7)) << 4);
                ldsm4(bh[bt], bbase + off);
                ldsm4(bl[bt], bbase + 16384 + off);
            }
            #pragma unroll
            for (int mt = 0; mt < 2; mt++)
                #pragma unroll
                for (int nt = 0; nt < 8; nt++) {
                    int bt = nt >> 1, s = (nt & 1) * 2;
                    mma_bf16(acc[mt][nt], ah[mt], bh[bt][s], bh[bt][s+1]);
                    mma_bf16(acc[mt][nt], al[mt], bh[bt][s], bh[bt][s+1]);
                    mma_bf16(acc[mt][nt], ah[mt], bl[bt][s], bl[bt][s+1]);
                }
        }
        __syncthreads();
        if (c + 2 < NC) issue(c + 2, buf);
    }

    // ---- epilogue ----
    #pragma unroll
    for (int mt = 0; mt < 2; mt++) {
        int row = tok0 + mwb + mt*16 + (lane >> 2);
        #pragma unroll
        for (int nt = 0; nt < 8; nt++) {
            int col = n0 + nwb + nt*8 + 2*(lane & 3);
            if (MODE == 0) {
                float* o = g_raw[which];
                *(float2*)(o + (size_t)row*512 + col) =
                    make_float2(acc[mt][nt][0], acc[mt][nt][1]);
                *(float2*)(o + (size_t)(row+8)*512 + col) =
                    make_float2(acc[mt][nt][2], acc[mt][nt][3]);
            } else {
                float b0 = sbias[col - n0], b1 = sbias[col - n0 + 1];
                *(float2*)(outp + (size_t)row*256 + col) =
                    make_float2(acc[mt][nt][0] + b0, acc[mt][nt][1] + b1);
                *(float2*)(outp + (size_t)(row+8)*256 + col) =
                    make_float2(acc[mt][nt][2] + b0, acc[mt][nt][3] + b1);
            }
        }
    }
}

// ---------------- x -> bf16 hi/lo planes ----------------
__global__ void xconv_kernel(const float* __restrict__ xI, const float* __restrict__ xM)
{
    const int im = blockIdx.y;
    const float* x = im ? xM : xI;
    size_t off = ((size_t)blockIdx.x*256 + threadIdx.x) * 8;
    float4 f0 = *(const float4*)(x + off);
    float4 f1 = *(const float4*)(x + off + 4);
    float vs[8] = {f0.x,f0.y,f0.z,f0.w,f1.x,f1.y,f1.z,f1.w};
    __nv_bfloat16 h[8], l[8];
    #pragma unroll
    for (int i = 0; i < 8; i++) {
        h[i] = __float2bfloat16(vs[i]);
        l[i] = __float2bfloat16(vs[i] - __bfloat162float(h[i]));
    }
    *(uint4*)(&g_xhi[im][off]) = *(uint4*)h;
    *(uint4*)(&g_xlo[im][off]) = *(uint4*)l;
}

// ---------------- normalize: bias + L2 norm + planes + Gu/s2 ----------------
// grid (TOK/32, 4)  which: 0=qI 1=qM 2=kI 3=kM ; 256 threads (8 warps x 4 tokens)
__global__ void __launch_bounds__(256) norm_kernel(
    const float* __restrict__ bqI, const float* __restrict__ bqM,
    const float* __restrict__ bkI, const float* __restrict__ bkM,
    const float* __restrict__ wgI, const float* __restrict__ wgM)
{
    const int which = blockIdx.y;
    const int tok0 = blockIdx.x * 32;
    const int b = tok0 >> 12;
    const float* bias = (which==0)?bqI:(which==1)?bqM:(which==2)?bkI:bkM;
    const float* wg = (which==0)?wgI:(which==1)?wgM:nullptr;
    const float* raw = g_raw[which];
    __nv_bfloat16* oh = g_phi[which];
    __nv_bfloat16* ol = g_plo[which];

    __shared__ float sGu[513];
    const int warp = threadIdx.x >> 5, lane = threadIdx.x & 31;

    float v[4][16];
    #pragma unroll
    for (int i = 0; i < 4; i++) {
        size_t base = (size_t)(tok0 + 4*warp + i)*512;
        #pragma unroll
        for (int j = 0; j < 16; j++)
            v[i][j] = raw[base + lane + 32*j] + __ldg(&bias[lane + 32*j]);
    }
    #pragma unroll
    for (int i = 0; i < 4; i++) {
        float ss = 0.f;
        #pragma unroll
        for (int j = 0; j < 16; j++) ss += v[i][j]*v[i][j];
        #pragma unroll
        for (int o = 16; o; o >>= 1) ss += __shfl_xor_sync(0xFFFFFFFFu, ss, o);
        float inv = 1.f / fmaxf(sqrtf(ss), 1e-12f);
        #pragma unroll
        for (int j = 0; j < 16; j++) v[i][j] *= inv;
    }
    // store hi/lo planes
    #pragma unroll
    for (int i = 0; i < 4; i++) {
        size_t base = (size_t)(tok0 + 4*warp + i)*512;
        #pragma unroll
        for (int j = 0; j < 16; j++) {
            __nv_bfloat16 h = __float2bfloat16(v[i][j]);
            oh[base + lane + 32*j] = h;
            ol[base + lane + 32*j] = __float2bfloat16(v[i][j] - __bfloat162float(h));
        }
    }
    if (which < 2) {
        for (int c = threadIdx.x; c < 513; c += 256) sGu[c] = 0.f;
        __syncthreads();
        float s[4];
        #pragma unroll
        for (int i = 0; i < 4; i++) {
            float t = 0.f;
            #pragma unroll
            for (int j = 0; j < 16; j++) t += v[i][j] * __ldg(&wg[lane + 32*j]);
            #pragma unroll
            for (int o = 16; o; o >>= 1) t += __shfl_xor_sync(0xFFFFFFFFu, t, o);
            s[i] = t;
        }
        #pragma unroll
        for (int j = 0; j < 16; j++) {
            float g = s[0]*v[0][j] + s[1]*v[1][j] + s[2]*v[2][j] + s[3]*v[3][j];
            atomicAdd(&sGu[lane + 32*j], g);
        }
        if (lane == 0)
            atomicAdd(&sGu[512], s[0]*s[0] + s[1]*s[1] + s[2]*s[2] + s[3]*s[3]);
        __syncthreads();
        float* accG = g_acc + ((size_t)b*2 + which)*513;
        for (int c = threadIdx.x; c < 513; c += 256) atomicAdd(&accG[c], sGu[c]);
    }
}

// ---------------- prep: W^T hi/lo planes, f_w^T, zero acc ----------------
__global__ void prep_kernel(const float* __restrict__ wqI, const float* __restrict__ wqM,
                            const float* __restrict__ wkI, const float* __restrict__ wkM,
                            const float* __restrict__ fw)
{
    int idx = blockIdx.x*256 + threadIdx.x;
    if (idx < 4*DD*DD) {
        int m = idx >> 18, r = idx & (DD*DD - 1);
        int n = r >> 9, k = r & 511;
        const float* W = (m==0)?wqI:(m==1)?wqM:(m==2)?wkI:wkM;
        float v = W[(size_t)k*DD + n];
        __nv_bfloat16 h = __float2bfloat16(v);
        g_Wthi[m][r] = h;
        g_Wtlo[m][r] = __float2bfloat16(v - __bfloat162float(h));
    } else if ((idx -= 4*DD*DD) < TD*DD) {
        int n = idx >> 9, e = idx & 511;
        g_fwT[idx] = fw[(size_t)e*TD + n];
    } else if ((idx -= TD*DD) < BB*2*513) {
        g_acc[idx] = 0.f;
    }
}

// ---------------- PFt = (p_i @ f_w)^T ----------------
__global__ void __launch_bounds__(256) pf_kernel(
    const float* __restrict__ p1, const float* __restrict__ p2,
    const float* __restrict__ p3, const float* __restrict__ p4,
    const float* __restrict__ fw)
{
    const float* P[4] = {p1, p2, p3, p4};
    const float* p = P[blockIdx.y];
    float* out = g_PFt[blockIdx.y];
    const int r0 = blockIdx.x * 32;
    __shared__ float sA[32][8];
    __shared__ float sF[8][256];
    const int warp = threadIdx.x >> 5, lane = threadIdx.x & 31;
    float acc[4][8];
    #pragma unroll
    for (int i = 0; i < 4; i++)
        #pragma unroll
        for (int j = 0; j < 8; j++) acc[i][j] = 0.f;
    for (int k0 = 0; k0 < DD; k0 += 8) {
        {
            int t = threadIdx.x >> 3, kk = threadIdx.x & 7;
            sA[t][kk] = p[(size_t)(r0 + t)*DD + k0 + kk];
        }
        #pragma unroll
        for (int i = 0; i < 2; i++) {
            int idx = threadIdx.x + 256*i;
            int kk = idx >> 6, dv = idx & 63;
            ((float4*)&sF[kk][0])[dv] = ((const float4*)(fw + (size_t)(k0+kk)*TD))[dv];
        }
        __syncthreads();
        #pragma unroll
        for (int kk = 0; kk < 8; kk++) {
            float a0 = sA[4*warp+0][kk], a1 = sA[4*warp+1][kk];
            float a2 = sA[4*warp+2][kk], a3 = sA[4*warp+3][kk];
            #pragma unroll
            for (int j = 0; j < 8; j++) {
                float w = sF[kk][lane + 32*j];
                acc[0][j] += a0*w; acc[1][j] += a1*w;
                acc[2][j] += a2*w; acc[3][j] += a3*w;
            }
        }
        __syncthreads();
    }
    #pragma unroll
    for (int i = 0; i < 4; i++)
        #pragma unroll
        for (int j = 0; j < 8; j++)
            out[(size_t)(lane + 32*j)*DD + r0 + 4*warp + i] = acc[i][j];
}

// ---------------- cvec ----------------
__global__ void cvec_kernel(const float* __restrict__ b1, const float* __restrict__ b2,
                            const float* __restrict__ b3, const float* __restrict__ b4,
                            const float* __restrict__ fb)
{
    int c = blockIdx.x, t = threadIdx.x;
    float p = 0.f;
    for (int e = t; e < DD; e += 128)
        p += (b1[e] + b2[e] + b3[e] + b4[e]) * g_fwT[(size_t)c*DD + e];
    #pragma unroll
    for (int o = 16; o; o >>= 1) p += __shfl_xor_sync(0xFFFFFFFFu, p, o);
    __shared__ float sp[4];
    if ((t & 31) == 0) sp[t >> 5] = p;
    __syncthreads();
    if (t == 0) g_cvec[c] = sp[0] + sp[1] + sp[2] + sp[3] + fb[c];
}

// ---------------- combined weights Wc^T (bf16 hi/lo) ----------------
// K segs (2048): [0,512)=kI rows, [512,1024)=kM rows, [1024,1536)=qI (f_w), [1536,2048)=qM (f_w)
__global__ void combine_kernel()
{
    int n = blockIdx.x, b = blockIdx.y, t = threadIdx.x;
    const float* acc = g_acc + (size_t)b*2*513;
    float nI = fmaxf(SCALE_F * sqrtf(acc[512]),       1e-12f);
    float nM = fmaxf(SCALE_F * sqrtf(acc[513 + 512]), 1e-12f);
    for (int k = t; k < 2048; k += 256) {
        float v;
        if (k < 1024) {
            int kk = k & 511;
            float GI = SCALE_F * acc[kk] / nI;
            float GM = SCALE_F * acc[513 + kk] / nM;
            if (k < 512) v = GI*g_PFt[0][(size_t)n*DD+kk] + GM*g_PFt[3][(size_t)n*DD+kk];
            else         v = GI*g_PFt[1][(size_t)n*DD+kk] + GM*g_PFt[2][(size_t)n*DD+kk];
        } else {
            v = g_fwT[(size_t)n*DD + (k & 511)];
        }
        __nv_bfloat16 h = __float2bfloat16(v);
        g_Wchi[b][(size_t)n*2048 + k] = h;
        g_Wclo[b][(size_t)n*2048 + k] = __float2bfloat16(v - __bfloat162float(h));
    }
}

// ---------------- launch ----------------
extern "C" void kernel_launch(void* const* d_in, const int* in_sizes, int n_in,
                              void* d_out, int out_size)
{
    const float* xI  = (const float*)d_in[0];
    const float* xM  = (const float*)d_in[1];
    const float* wqI = (const float*)d_in[2];
    const float* bqI = (const float*)d_in[3];
    const float* wkI = (const float*)d_in[4];
    const float* bkI = (const float*)d_in[5];
    const float* wqM = (const float*)d_in[6];
    const float* bqM = (const float*)d_in[7];
    const float* wkM = (const float*)d_in[8];
    const float* bkM = (const float*)d_in[9];
    const float* wgI = (const float*)d_in[10];
    const float* wgM = (const float*)d_in[11];
    const float* p1w = (const float*)d_in[12];
    const float* p1b = (const float*)d_in[13];
    const float* p2w = (const float*)d_in[14];
    const float* p2b = (const float*)d_in[15];
    const float* p3w = (const float*)d_in[16];
    const float* p3b = (const float*)d_in[17];
    const float* p4w = (const float*)d_in[18];
    const float* p4b = (const float*)d_in[19];
    const float* fw  = (const float*)d_in[20];
    const float* fb  = (const float*)d_in[21];
    float* out = (float*)d_out;

    cudaFuncSetAttribute(mma_gemm<0>, cudaFuncAttributeMaxDynamicSharedMemorySize, SMEM_TOTAL);
    cudaFuncSetAttribute(mma_gemm<1>, cudaFuncAttributeMaxDynamicSharedMemorySize, SMEM_TOTAL);

    prep_kernel<<<4642, 256>>>(wqI, wqM, wkI, wkM, fw);
    xconv_kernel<<<dim3(TOK*DD/(256*8), 2), 256>>>(xI, xM);
    mma_gemm<0><<<dim3(TOK/128, 4, 4), 256, SMEM_TOTAL>>>(nullptr);
    norm_kernel<<<dim3(TOK/32, 4), 256>>>(bqI, bqM, bkI, bkM, wgI, wgM);
    pf_kernel<<<dim3(16, 4), 256>>>(p1w, p2w, p3w, p4w, fw);
    cvec_kernel<<<TD, 128>>>(p1b, p2b, p3b, p4b, fb);
    combine_kernel<<<dim3(TD, BB), 256>>>();
    mma_gemm<1><<<dim3(TOK/128, 2, 1), 256, SMEM_TOTAL>>>(out);
}

// round 7
// speedup vs baseline: 6.4441x; 2.1449x over previous
#include <cuda_runtime.h>
#include <cuda_fp16.h>
#include <math.h>
#include <stdint.h>

#define BB 8
#define NN 4096
#define DD 512
#define TD 256
#define TOK (BB*NN)
#define SCALE_F 0.0625f

// ---------------- static scratch ----------------
__device__ __align__(16) __half g_xh[2][(size_t)TOK*DD];     // x fp16 (I, M)
__device__ __align__(16) __half g_raw16[4][(size_t)TOK*DD];  // proj out + bias, fp16
__device__ __align__(16) __half g_ph[4][(size_t)TOK*DD];     // normalized q/k fp16 [qI,qM,kI,kM]
__device__ __align__(16) __half g_Wth[4][DD*DD];             // W^T fp16 [mat][n][k]
__device__ __align__(16) __half g_Wch[BB][TD*2048];          // combined W^T fp16 [b][n][k]
__device__ float g_fwT[TD*DD];                               // f_w^T [n][e]
__device__ float g_PFt[4][TD*DD];                            // (p_i@f_w)^T [n][k]
__device__ float g_acc[BB*2*513];
__device__ float g_cvec[TD];

// ---------------- helpers ----------------
__device__ __forceinline__ uint32_t smem_u32(const void* p) {
    uint32_t a;
    asm("{ .reg .u64 t; cvta.to.shared.u64 t, %1; cvt.u32.u64 %0, t; }" : "=r"(a) : "l"(p));
    return a;
}
__device__ __forceinline__ void cp16(uint32_t s, const void* g) {
    asm volatile("cp.async.cg.shared.global [%0], [%1], 16;" :: "r"(s), "l"(g));
}
__device__ __forceinline__ void cp_commit() { asm volatile("cp.async.commit_group;"); }
__device__ __forceinline__ void cp_wait1()  { asm volatile("cp.async.wait_group 1;"); }
__device__ __forceinline__ void cp_wait0()  { asm volatile("cp.async.wait_group 0;"); }
__device__ __forceinline__ void ldsm4(uint32_t* r, uint32_t addr) {
    asm volatile("ldmatrix.sync.aligned.m8n8.x4.shared.b16 {%0,%1,%2,%3}, [%4];"
        : "=r"(r[0]), "=r"(r[1]), "=r"(r[2]), "=r"(r[3]) : "r"(addr));
}
__device__ __forceinline__ void mma_f16(float* c, const uint32_t* a, uint32_t b0, uint32_t b1) {
    asm volatile("mma.sync.aligned.m16n8k16.row.col.f32.f16.f16.f32 "
        "{%0,%1,%2,%3}, {%4,%5,%6,%7}, {%8,%9}, {%0,%1,%2,%3};"
        : "+f"(c[0]), "+f"(c[1]), "+f"(c[2]), "+f"(c[3])
        : "r"(a[0]), "r"(a[1]), "r"(a[2]), "r"(a[3]), "r"(b0), "r"(b1));
}

// SMEM per buffer: A 16KB + B 16KB = 32KB; double buffered 64KB
#define BUFSZ 32768
#define SMEM_TOTAL 65536

// ---------------- MMA GEMM (MODE 0 = proj -> raw16 (+bias); MODE 1 = final -> out) ----
// grid: (TOK/128, ntiles, which)  block 256
template<int MODE>
__global__ void __launch_bounds__(256) mma_gemm(
    const float* __restrict__ bqI, const float* __restrict__ bqM,
    const float* __restrict__ bkI, const float* __restrict__ bkM,
    float* __restrict__ outp)
{
    extern __shared__ char smem[];
    const uint32_t sb = smem_u32(smem);
    __shared__ float sbias[128];

    const int tid = threadIdx.x, wid = tid >> 5, lane = tid & 31;
    const int tok0 = blockIdx.x * 128;
    const int n0   = blockIdx.y * 128;
    const int which = (MODE == 0) ? blockIdx.z : 0;
    const int batch = tok0 >> 12;
    const int NC = (MODE == 0) ? 8 : 32;

    if (MODE == 0) {
        const float* bias = (which==0)?bqI:(which==1)?bqM:(which==2)?bkI:bkM;
        if (tid < 128) sbias[tid] = bias[n0 + tid];
    } else {
        if (tid < 128) sbias[tid] = g_cvec[n0 + tid];
    }

    const int xsel = which & 1;

    // ---- issue chunk c (Kc=64) into buffer via cp.async ----
    auto issue = [&](int c, int buf) {
        uint32_t abase = sb + buf*BUFSZ;
        uint32_t bbase = abase + 16384;
        // A: 128 rows x 64 halves (8 x 16B per row)
        #pragma unroll
        for (int it = 0; it < 4; it++) {
            int v = it*256 + tid;
            int r = v >> 3, u = v & 7;
            const __half* src;
            if (MODE == 0) {
                src = g_xh[xsel] + (size_t)(tok0 + r)*512 + c*64 + u*8;
            } else {
                int mat = (c >> 3) ^ 2;     // k-segs: kI,kM,qI,qM -> mats 2,3,0,1
                src = g_ph[mat] + (size_t)(tok0 + r)*512 + (c & 7)*64 + u*8;
            }
            cp16(abase + r*128 + ((u ^ (r & 7)) << 4), src);
        }
        // B: 128 n-rows x 64 halves
        #pragma unroll
        for (int it = 0; it < 4; it++) {
            int v = it*256 + tid;
            int r = v >> 3, u = v & 7;
            const __half* src;
            if (MODE == 0) {
                src = g_Wth[which] + (size_t)(n0 + r)*512 + c*64 + u*8;
            } else {
                src = g_Wch[batch] + (size_t)(n0 + r)*2048 + c*64 + u*8;
            }
            cp16(bbase + r*128 + ((u ^ (r & 7)) << 4), src);
        }
        cp_commit();
    };

    float acc[2][8][4];
    #pragma unroll
    for (int mt = 0; mt < 2; mt++)
        #pragma unroll
        for (int nt = 0; nt < 8; nt++)
            #pragma unroll
            for (int e = 0; e < 4; e++) acc[mt][nt][e] = 0.f;

    const int wm = wid >> 1, wn = wid & 1;      // warps 4x2 -> 32m x 64n per warp
    const int mwb = wm * 32, nwb = wn * 64;

    issue(0, 0);
    issue(1, 1);

    for (int c = 0; c < NC; c++) {
        if (c < NC - 1) cp_wait1(); else cp_wait0();
        __syncthreads();
        const int buf = c & 1;
        uint32_t abase = sb + buf*BUFSZ;
        uint32_t bbase = abase + 16384;

        #pragma unroll
        for (int k16 = 0; k16 < 4; k16++) {
            uint32_t ah[2][4], bh[4][4];
            #pragma unroll
            for (int mt = 0; mt < 2; mt++) {
                int row = mwb + mt*16 + (lane & 15);
                int kb  = k16*2 + (lane >> 4);
                ldsm4(ah[mt], abase + row*128 + ((kb ^ (row & 7)) << 4));
            }
            #pragma unroll
            for (int bt = 0; bt < 4; bt++) {
                int row = nwb + bt*16 + ((lane >> 4) << 3) + (lane & 7);
                int kb  = k16*2 + ((lane >> 3) & 1);
                ldsm4(bh[bt], bbase + row*128 + ((kb ^ (row & 7)) << 4));
            }
            #pragma unroll
            for (int mt = 0; mt < 2; mt++)
                #pragma unroll
                for (int nt = 0; nt < 8; nt++) {
                    int bt = nt >> 1, s = (nt & 1) * 2;
                    mma_f16(acc[mt][nt], ah[mt], bh[bt][s], bh[bt][s+1]);
                }
        }
        __syncthreads();
        if (c + 2 < NC) issue(c + 2, buf);
    }

    // ---- epilogue ----
    #pragma unroll
    for (int mt = 0; mt < 2; mt++) {
        int row = tok0 + mwb + mt*16 + (lane >> 2);
        #pragma unroll
        for (int nt = 0; nt < 8; nt++) {
            int col = n0 + nwb + nt*8 + 2*(lane & 3);
            float b0 = sbias[col - n0], b1 = sbias[col - n0 + 1];
            if (MODE == 0) {
                __half* o = g_raw16[which];
                *(__half2*)(o + (size_t)row*512 + col) =
                    __floats2half2_rn(acc[mt][nt][0] + b0, acc[mt][nt][1] + b1);
                *(__half2*)(o + (size_t)(row+8)*512 + col) =
                    __floats2half2_rn(acc[mt][nt][2] + b0, acc[mt][nt][3] + b1);
            } else {
                *(float2*)(outp + (size_t)row*256 + col) =
                    make_float2(acc[mt][nt][0] + b0, acc[mt][nt][1] + b1);
                *(float2*)(outp + (size_t)(row+8)*256 + col) =
                    make_float2(acc[mt][nt][2] + b0, acc[mt][nt][3] + b1);
            }
        }
    }
}

// ---------------- x -> fp16 ----------------
__global__ void xconv_kernel(const float* __restrict__ xI, const float* __restrict__ xM)
{
    const int im = blockIdx.y;
    const float* x = im ? xM : xI;
    size_t off = ((size_t)blockIdx.x*256 + threadIdx.x) * 8;
    float4 f0 = *(const float4*)(x + off);
    float4 f1 = *(const float4*)(x + off + 4);
    __half h[8];
    h[0]=__float2half(f0.x); h[1]=__float2half(f0.y);
    h[2]=__float2half(f0.z); h[3]=__float2half(f0.w);
    h[4]=__float2half(f1.x); h[5]=__float2half(f1.y);
    h[6]=__float2half(f1.z); h[7]=__float2half(f1.w);
    *(uint4*)(&g_xh[im][off]) = *(uint4*)h;
}

// ---------------- normalize: L2 norm + fp16 planes + Gu/s2 (bias already in raw) ----
// grid (TOK/32, 4)  which: 0=qI 1=qM 2=kI 3=kM ; 256 threads (8 warps x 4 tokens)
__global__ void __launch_bounds__(256) norm_kernel(
    const float* __restrict__ wgI, const float* __restrict__ wgM)
{
    const int which = blockIdx.y;
    const int tok0 = blockIdx.x * 32;
    const int b = tok0 >> 12;
    const float* wg = (which==0)?wgI:(which==1)?wgM:nullptr;
    const __half* raw = g_raw16[which];
    __half* oh = g_ph[which];

    __shared__ float sGu[513];
    const int warp = threadIdx.x >> 5, lane = threadIdx.x & 31;

    float v[4][16];
    #pragma unroll
    for (int i = 0; i < 4; i++) {
        size_t base = (size_t)(tok0 + 4*warp + i)*512;
        #pragma unroll
        for (int j = 0; j < 16; j++)
            v[i][j] = __half2float(raw[base + lane + 32*j]);
    }
    #pragma unroll
    for (int i = 0; i < 4; i++) {
        float ss = 0.f;
        #pragma unroll
        for (int j = 0; j < 16; j++) ss += v[i][j]*v[i][j];
        #pragma unroll
        for (int o = 16; o; o >>= 1) ss += __shfl_xor_sync(0xFFFFFFFFu, ss, o);
        float inv = 1.f / fmaxf(sqrtf(ss), 1e-12f);
        #pragma unroll
        for (int j = 0; j < 16; j++) v[i][j] *= inv;
    }
    #pragma unroll
    for (int i = 0; i < 4; i++) {
        size_t base = (size_t)(tok0 + 4*warp + i)*512;
        #pragma unroll
        for (int j = 0; j < 16; j++)
            oh[base + lane + 32*j] = __float2half(v[i][j]);
    }
    if (which < 2) {
        for (int c = threadIdx.x; c < 513; c += 256) sGu[c] = 0.f;
        __syncthreads();
        float s[4];
        #pragma unroll
        for (int i = 0; i < 4; i++) {
            float t = 0.f;
            #pragma unroll
            for (int j = 0; j < 16; j++) t += v[i][j] * __ldg(&wg[lane + 32*j]);
            #pragma unroll
            for (int o = 16; o; o >>= 1) t += __shfl_xor_sync(0xFFFFFFFFu, t, o);
            s[i] = t;
        }
        #pragma unroll
        for (int j = 0; j < 16; j++) {
            float g = s[0]*v[0][j] + s[1]*v[1][j] + s[2]*v[2][j] + s[3]*v[3][j];
            atomicAdd(&sGu[lane + 32*j], g);
        }
        if (lane == 0)
            atomicAdd(&sGu[512], s[0]*s[0] + s[1]*s[1] + s[2]*s[2] + s[3]*s[3]);
        __syncthreads();
        float* accG = g_acc + ((size_t)b*2 + which)*513;
        for (int c = threadIdx.x; c < 513; c += 256) atomicAdd(&accG[c], sGu[c]);
    }
}

// ---------------- prep: W^T fp16, f_w^T, zero acc ----------------
__global__ void prep_kernel(const float* __restrict__ wqI, const float* __restrict__ wqM,
                            const float* __restrict__ wkI, const float* __restrict__ wkM,
                            const float* __restrict__ fw)
{
    int idx = blockIdx.x*256 + threadIdx.x;
    if (idx < 4*DD*DD) {
        int m = idx >> 18, r = idx & (DD*DD - 1);
        int n = r >> 9, k = r & 511;
        const float* W = (m==0)?wqI:(m==1)?wqM:(m==2)?wkI:wkM;
        g_Wth[m][r] = __float2half(W[(size_t)k*DD + n]);
    } else if ((idx -= 4*DD*DD) < TD*DD) {
        int n = idx >> 9, e = idx & 511;
        g_fwT[idx] = fw[(size_t)e*TD + n];
    } else if ((idx -= TD*DD) < BB*2*513) {
        g_acc[idx] = 0.f;
    }
}

// ---------------- PFt = (p_i @ f_w)^T ----------------
__global__ void __launch_bounds__(256) pf_kernel(
    const float* __restrict__ p1, const float* __restrict__ p2,
    const float* __restrict__ p3, const float* __restrict__ p4,
    const float* __restrict__ fw)
{
    const float* P[4] = {p1, p2, p3, p4};
    const float* p = P[blockIdx.y];
    float* out = g_PFt[blockIdx.y];
    const int r0 = blockIdx.x * 32;
    __shared__ float sA[32][8];
    __shared__ float sF[8][256];
    const int warp = threadIdx.x >> 5, lane = threadIdx.x & 31;
    float acc[4][8];
    #pragma unroll
    for (int i = 0; i < 4; i++)
        #pragma unroll
        for (int j = 0; j < 8; j++) acc[i][j] = 0.f;
    for (int k0 = 0; k0 < DD; k0 += 8) {
        {
            int t = threadIdx.x >> 3, kk = threadIdx.x & 7;
            sA[t][kk] = p[(size_t)(r0 + t)*DD + k0 + kk];
        }
        #pragma unroll
        for (int i = 0; i < 2; i++) {
            int idx = threadIdx.x + 256*i;
            int kk = idx >> 6, dv = idx & 63;
            ((float4*)&sF[kk][0])[dv] = ((const float4*)(fw + (size_t)(k0+kk)*TD))[dv];
        }
        __syncthreads();
        #pragma unroll
        for (int kk = 0; kk < 8; kk++) {
            float a0 = sA[4*warp+0][kk], a1 = sA[4*warp+1][kk];
            float a2 = sA[4*warp+2][kk], a3 = sA[4*warp+3][kk];
            #pragma unroll
            for (int j = 0; j < 8; j++) {
                float w = sF[kk][lane + 32*j];
                acc[0][j] += a0*w; acc[1][j] += a1*w;
                acc[2][j] += a2*w; acc[3][j] += a3*w;
            }
        }
        __syncthreads();
    }
    #pragma unroll
    for (int i = 0; i < 4; i++)
        #pragma unroll
        for (int j = 0; j < 8; j++)
            out[(size_t)(lane + 32*j)*DD + r0 + 4*warp + i] = acc[i][j];
}

// ---------------- cvec ----------------
__global__ void cvec_kernel(const float* __restrict__ b1, const float* __restrict__ b2,
                            const float* __restrict__ b3, const float* __restrict__ b4,
                            const float* __restrict__ fb)
{
    int c = blockIdx.x, t = threadIdx.x;
    float p = 0.f;
    for (int e = t; e < DD; e += 128)
        p += (b1[e] + b2[e] + b3[e] + b4[e]) * g_fwT[(size_t)c*DD + e];
    #pragma unroll
    for (int o = 16; o; o >>= 1) p += __shfl_xor_sync(0xFFFFFFFFu, p, o);
    __shared__ float sp[4];
    if ((t & 31) == 0) sp[t >> 5] = p;
    __syncthreads();
    if (t == 0) g_cvec[c] = sp[0] + sp[1] + sp[2] + sp[3] + fb[c];
}

// ---------------- combined weights Wc^T fp16 ----------------
// K segs (2048): [0,512)=kI, [512,1024)=kM, [1024,1536)=qI (f_w), [1536,2048)=qM (f_w)
__global__ void combine_kernel()
{
    int n = blockIdx.x, b = blockIdx.y, t = threadIdx.x;
    const float* acc = g_acc + (size_t)b*2*513;
    float nI = fmaxf(SCALE_F * sqrtf(acc[512]),       1e-12f);
    float nM = fmaxf(SCALE_F * sqrtf(acc[513 + 512]), 1e-12f);
    for (int k = t; k < 2048; k += 256) {
        float v;
        if (k < 1024) {
            int kk = k & 511;
            float GI = SCALE_F * acc[kk] / nI;
            float GM = SCALE_F * acc[513 + kk] / nM;
            if (k < 512) v = GI*g_PFt[0][(size_t)n*DD+kk] + GM*g_PFt[3][(size_t)n*DD+kk];
            else         v = GI*g_PFt[1][(size_t)n*DD+kk] + GM*g_PFt[2][(size_t)n*DD+kk];
        } else {
            v = g_fwT[(size_t)n*DD + (k & 511)];
        }
        g_Wch[b][(size_t)n*2048 + k] = __float2half(v);
    }
}

// ---------------- launch ----------------
extern "C" void kernel_launch(void* const* d_in, const int* in_sizes, int n_in,
                              void* d_out, int out_size)
{
    const float* xI  = (const float*)d_in[0];
    const float* xM  = (const float*)d_in[1];
    const float* wqI = (const float*)d_in[2];
    const float* bqI = (const float*)d_in[3];
    const float* wkI = (const float*)d_in[4];
    const float* bkI = (const float*)d_in[5];
    const float* wqM = (const float*)d_in[6];
    const float* bqM = (const float*)d_in[7];
    const float* wkM = (const float*)d_in[8];
    const float* bkM = (const float*)d_in[9];
    const float* wgI = (const float*)d_in[10];
    const float* wgM = (const float*)d_in[11];
    const float* p1w = (const float*)d_in[12];
    const float* p1b = (const float*)d_in[13];
    const float* p2w = (const float*)d_in[14];
    const float* p2b = (const float*)d_in[15];
    const float* p3w = (const float*)d_in[16];
    const float* p3b = (const float*)d_in[17];
    const float* p4w = (const float*)d_in[18];
    const float* p4b = (const float*)d_in[19];
    const float* fw  = (const float*)d_in[20];
    const float* fb  = (const float*)d_in[21];
    float* out = (float*)d_out;

    cudaFuncSetAttribute(mma_gemm<0>, cudaFuncAttributeMaxDynamicSharedMemorySize, SMEM_TOTAL);
    cudaFuncSetAttribute(mma_gemm<1>, cudaFuncAttributeMaxDynamicSharedMemorySize, SMEM_TOTAL);

    prep_kernel<<<4642, 256>>>(wqI, wqM, wkI, wkM, fw);
    xconv_kernel<<<dim3(TOK*DD/(256*8), 2), 256>>>(xI, xM);
    mma_gemm<0><<<dim3(TOK/128, 4, 4), 256, SMEM_TOTAL>>>(bqI, bqM, bkI, bkM, nullptr);
    norm_kernel<<<dim3(TOK/32, 4), 256>>>(wgI, wgM);
    pf_kernel<<<dim3(16, 4), 256>>>(p1w, p2w, p3w, p4w, fw);
    cvec_kernel<<<TD, 128>>>(p1b, p2b, p3b, p4b, fb);
    combine_kernel<<<dim3(TD, BB), 256>>>();
    mma_gemm<1><<<dim3(TOK/128, 2, 1), 256, SMEM_TOTAL>>>(bqI, bqM, bkI, bkM, out);
}